// round 2
// baseline (speedup 1.0000x reference)
#include <cuda_runtime.h>

typedef unsigned long long u64;

#define NMAX 500000
#define EMAX 1000000
#define GMAX 5000

// ---- persistent scratch (no runtime allocation allowed) ----
__device__ float4 g_h0[NMAX * 8];        // [N,32]  post-pre-layer features
__device__ float4 g_acc1[NMAX * 16];     // [N,64]  layer-1 pre-activation accumulator
__device__ float4 g_acc2[GMAX * 16];     // [G,64]  layer-2 pre-activation (targets only)
__device__ int    g_cnt[3 * NMAX];       // edge count per (rel,dst)
__device__ float  g_inv[3 * NMAX];       // 1/max(cnt,1)
__device__ int    g_rank[NMAX];          // node -> graph rank (or -1)
__device__ int2   g_eb[3 * (size_t)EMAX];// relation-partitioned edges (src,dst)
__device__ int4   g_tl[EMAX];            // target edges (src, grank, rel, dst)
__device__ int    g_ctr[8];              // [0..2]=bucket counts, [3]=target edge count

// ---- packed f32x2 helpers ----
__device__ __forceinline__ u64 pack2(float x, float y) {
    u64 d;
    asm("mov.b64 %0, {%1, %2};" : "=l"(d) : "r"(__float_as_uint(x)), "r"(__float_as_uint(y)));
    return d;
}
__device__ __forceinline__ void unpack2(u64 v, float& x, float& y) {
    unsigned a, b;
    asm("mov.b64 {%0, %1}, %2;" : "=r"(a), "=r"(b) : "l"(v));
    x = __uint_as_float(a); y = __uint_as_float(b);
}
__device__ __forceinline__ u64 fma2(u64 a, u64 b, u64 c) {
    u64 d;
    asm("fma.rn.f32x2 %0, %1, %2, %3;" : "=l"(d) : "l"(a), "l"(b), "l"(c));
    return d;
}
__device__ __forceinline__ u64 mul2(u64 a, u64 b) {
    u64 d;
    asm("mul.rn.f32x2 %0, %1, %2;" : "=l"(d) : "l"(a), "l"(b));
    return d;
}
__device__ __forceinline__ void red4(float* p, float a, float b, float c, float d) {
    asm volatile("red.global.add.v4.f32 [%0], {%1, %2, %3, %4};"
                 :: "l"(p), "f"(a), "f"(b), "f"(c), "f"(d) : "memory");
}

// ---- init: zero counters + counts, clear rank map ----
__global__ void k_init(int n, int n3) {
    int i = blockIdx.x * blockDim.x + threadIdx.x;
    int stride = gridDim.x * blockDim.x;
    for (int j = i; j < n3; j += stride) g_cnt[j] = 0;
    for (int j = i; j < n;  j += stride) g_rank[j] = -1;
    if (i < 8) g_ctr[i] = 0;
}

__global__ void k_rank(const int* __restrict__ ptr, int G) {
    int g = blockIdx.x * blockDim.x + threadIdx.x;
    if (g < G) g_rank[ptr[g + 1] - 1] = g;
}

// ---- partition edges by relation, count per (rel,dst), collect target edges ----
__global__ void k_part(const int* __restrict__ ei, const int* __restrict__ et, int E, int n) {
    int e = blockIdx.x * blockDim.x + threadIdx.x;
    if (e >= E) return;
    int s = ei[e];
    int d = ei[E + e];
    int r = et[e];
    atomicAdd(&g_cnt[r * n + d], 1);
    int p = atomicAdd(&g_ctr[r], 1);
    g_eb[(size_t)r * EMAX + p] = make_int2(s, d);
    int rk = g_rank[d];
    if (rk >= 0) {
        int q = atomicAdd(&g_ctr[3], 1);
        g_tl[q] = make_int4(s, rk, r, d);
    }
}

__global__ void k_inv(int n3) {
    int i = blockIdx.x * blockDim.x + threadIdx.x;
    int stride = gridDim.x * blockDim.x;
    for (int j = i; j < n3; j += stride)
        g_inv[j] = 1.0f / fmaxf((float)g_cnt[j], 1.0f);
}

// ---- fused: embedding concat -> pre layer (relu) -> h0, and acc1 = b1 + h0 @ w1_root ----
__global__ __launch_bounds__(256) void k_node1(
    const int* __restrict__ x, const float* __restrict__ se, const float* __restrict__ ce,
    const float* __restrict__ pw, const float* __restrict__ pb,
    const float* __restrict__ wr, const float* __restrict__ b1, int n)
{
    __shared__ __align__(16) float s_pw[512];    // [16,32]
    __shared__ __align__(16) float s_wr[2048];   // [32,64]
    __shared__ float s_pb[32];
    __shared__ float s_b1[64];
    int t = threadIdx.x;
    for (int j = t; j < 512;  j += 256) s_pw[j] = pw[j];
    for (int j = t; j < 2048; j += 256) s_wr[j] = wr[j];
    if (t < 32) s_pb[t] = pb[t];
    if (t < 64) s_b1[t] = b1[t];
    __syncthreads();

    int i = blockIdx.x * 256 + t;
    if (i >= n) return;

    int x0 = x[2 * i], x1 = x[2 * i + 1];
    float v[16];
    const float4* sp = (const float4*)(se + x0 * 8);
    const float4* cp = (const float4*)(ce + x1 * 8);
    ((float4*)v)[0] = sp[0]; ((float4*)v)[1] = sp[1];
    ((float4*)v)[2] = cp[0]; ((float4*)v)[3] = cp[1];

    // pre layer: 16 -> 32
    u64 m1[16];
#pragma unroll
    for (int j = 0; j < 16; j++) m1[j] = pack2(s_pb[2 * j], s_pb[2 * j + 1]);
#pragma unroll
    for (int k = 0; k < 16; k++) {
        u64 h2 = pack2(v[k], v[k]);
        const ulonglong2* row = (const ulonglong2*)(s_pw + k * 32);
#pragma unroll
        for (int j = 0; j < 8; j++) {
            ulonglong2 w = row[j];
            m1[2 * j]     = fma2(h2, w.x, m1[2 * j]);
            m1[2 * j + 1] = fma2(h2, w.y, m1[2 * j + 1]);
        }
    }
    float h[32];
#pragma unroll
    for (int j = 0; j < 16; j++) {
        float a, b; unpack2(m1[j], a, b);
        h[2 * j] = fmaxf(a, 0.f); h[2 * j + 1] = fmaxf(b, 0.f);
    }
    float4* h0p = g_h0 + (size_t)i * 8;
#pragma unroll
    for (int j = 0; j < 8; j++) h0p[j] = ((float4*)h)[j];

    // root term of layer 1: acc1 = b1 + h @ w1_root
    u64 m2[32];
#pragma unroll
    for (int j = 0; j < 32; j++) m2[j] = pack2(s_b1[2 * j], s_b1[2 * j + 1]);
#pragma unroll 4
    for (int k = 0; k < 32; k++) {
        u64 h2 = pack2(h[k], h[k]);
        const ulonglong2* row = (const ulonglong2*)(s_wr + k * 64);
#pragma unroll
        for (int j = 0; j < 16; j++) {
            ulonglong2 w = row[j];
            m2[2 * j]     = fma2(h2, w.x, m2[2 * j]);
            m2[2 * j + 1] = fma2(h2, w.y, m2[2 * j + 1]);
        }
    }
    float o[64];
#pragma unroll
    for (int j = 0; j < 32; j++) unpack2(m2[j], o[2 * j], o[2 * j + 1]);
    float4* ap = g_acc1 + (size_t)i * 16;
#pragma unroll
    for (int j = 0; j < 16; j++) ap[j] = ((float4*)o)[j];
}

// ---- layer-1 edge pass: per edge, m = h0[src] @ W_r * inv(cnt), scatter-add into acc1[dst] ----
__global__ __launch_bounds__(256) void k_edge1(const float* __restrict__ w1rel, int n) {
    int r = blockIdx.y;
    __shared__ __align__(16) float Ws[2048];  // [32,64] for this relation
    const float* wsrc = w1rel + r * 2048;
    for (int j = threadIdx.x; j < 2048; j += 256) Ws[j] = wsrc[j];
    __syncthreads();

    int cnt = g_ctr[r];
    for (int idx = blockIdx.x * 256 + threadIdx.x; idx < cnt; idx += gridDim.x * 256) {
        int2 e = g_eb[(size_t)r * EMAX + idx];
        float h[32];
        const float4* hp = (const float4*)(g_h0 + (size_t)e.x * 8);
#pragma unroll
        for (int j = 0; j < 8; j++) ((float4*)h)[j] = hp[j];
        float inv = g_inv[(size_t)r * n + e.y];

        u64 m[32];
#pragma unroll
        for (int j = 0; j < 32; j++) m[j] = 0ull;
#pragma unroll 4
        for (int k = 0; k < 32; k++) {
            u64 h2 = pack2(h[k], h[k]);
            const ulonglong2* row = (const ulonglong2*)(Ws + k * 64);
#pragma unroll
            for (int j = 0; j < 16; j++) {
                ulonglong2 w = row[j];
                m[2 * j]     = fma2(h2, w.x, m[2 * j]);
                m[2 * j + 1] = fma2(h2, w.y, m[2 * j + 1]);
            }
        }
        u64 iv = pack2(inv, inv);
        float* dp = (float*)(g_acc1 + (size_t)e.y * 16);
#pragma unroll
        for (int j = 0; j < 16; j++) {
            float a0, a1, a2, a3;
            unpack2(mul2(m[2 * j], iv), a0, a1);
            unpack2(mul2(m[2 * j + 1], iv), a2, a3);
            red4(dp + 4 * j, a0, a1, a2, a3);
        }
    }
}

// ---- layer-2 root term, targets only: acc2[g] = b2 + relu(acc1[tgt]) @ w2_root ----
__global__ __launch_bounds__(256) void k_node2(
    const int* __restrict__ ptr, const float* __restrict__ w2root,
    const float* __restrict__ b2, int G)
{
    __shared__ __align__(16) float Ws[4096];  // [64,64]
    for (int j = threadIdx.x; j < 4096; j += 256) Ws[j] = w2root[j];
    __syncthreads();
    int g = blockIdx.x * 256 + threadIdx.x;
    if (g >= G) return;
    int node = ptr[g + 1] - 1;

    float h[64];
    const float4* hp = (const float4*)(g_acc1 + (size_t)node * 16);
#pragma unroll
    for (int j = 0; j < 16; j++) {
        float4 w = hp[j];
        w.x = fmaxf(w.x, 0.f); w.y = fmaxf(w.y, 0.f);
        w.z = fmaxf(w.z, 0.f); w.w = fmaxf(w.w, 0.f);
        ((float4*)h)[j] = w;
    }
    u64 m[32];
#pragma unroll
    for (int j = 0; j < 32; j++) m[j] = pack2(b2[2 * j], b2[2 * j + 1]);
#pragma unroll 4
    for (int k = 0; k < 64; k++) {
        u64 h2 = pack2(h[k], h[k]);
        const ulonglong2* row = (const ulonglong2*)(Ws + k * 64);
#pragma unroll
        for (int j = 0; j < 16; j++) {
            ulonglong2 w = row[j];
            m[2 * j]     = fma2(h2, w.x, m[2 * j]);
            m[2 * j + 1] = fma2(h2, w.y, m[2 * j + 1]);
        }
    }
    float o[64];
#pragma unroll
    for (int j = 0; j < 32; j++) unpack2(m[j], o[2 * j], o[2 * j + 1]);
    float4* ap = g_acc2 + (size_t)g * 16;
#pragma unroll
    for (int j = 0; j < 16; j++) ap[j] = ((float4*)o)[j];
}

// ---- layer-2 edge pass: only edges landing on target nodes (~E*G/N of them) ----
__global__ __launch_bounds__(256) void k_edge2(const float* __restrict__ w2rel, int n) {
    __shared__ __align__(16) float Ws[12288];  // [3,64,64] = 48KB
    for (int j = threadIdx.x; j < 12288; j += 256) Ws[j] = w2rel[j];
    __syncthreads();
    int cnt = g_ctr[3];
    for (int idx = blockIdx.x * 256 + threadIdx.x; idx < cnt; idx += gridDim.x * 256) {
        int4 e = g_tl[idx];  // x=src, y=grank, z=rel, w=dst
        float h[64];
        const float4* hp = (const float4*)(g_acc1 + (size_t)e.x * 16);
#pragma unroll
        for (int j = 0; j < 16; j++) {
            float4 w = hp[j];
            w.x = fmaxf(w.x, 0.f); w.y = fmaxf(w.y, 0.f);
            w.z = fmaxf(w.z, 0.f); w.w = fmaxf(w.w, 0.f);
            ((float4*)h)[j] = w;
        }
        float inv = g_inv[(size_t)e.z * n + e.w];
        const float* wb = Ws + e.z * 4096;

        u64 m[32];
#pragma unroll
        for (int j = 0; j < 32; j++) m[j] = 0ull;
#pragma unroll 4
        for (int k = 0; k < 64; k++) {
            u64 h2 = pack2(h[k], h[k]);
            const ulonglong2* row = (const ulonglong2*)(wb + k * 64);
#pragma unroll
            for (int j = 0; j < 16; j++) {
                ulonglong2 w = row[j];
                m[2 * j]     = fma2(h2, w.x, m[2 * j]);
                m[2 * j + 1] = fma2(h2, w.y, m[2 * j + 1]);
            }
        }
        u64 iv = pack2(inv, inv);
        float* dp = (float*)(g_acc2 + (size_t)e.y * 16);
#pragma unroll
        for (int j = 0; j < 16; j++) {
            float a0, a1, a2, a3;
            unpack2(mul2(m[2 * j], iv), a0, a1);
            unpack2(mul2(m[2 * j + 1], iv), a2, a3);
            red4(dp + 4 * j, a0, a1, a2, a3);
        }
    }
}

// ---- classifier: out[g] = relu(acc2[g]) @ cls_w + cls_b ----
__global__ void k_cls(const float* __restrict__ cw, const float* __restrict__ cb,
                      float* __restrict__ out, int G)
{
    __shared__ float Ws[640];
    __shared__ float sb[16];
    for (int j = threadIdx.x; j < 640; j += blockDim.x) Ws[j] = cw[j];
    if (threadIdx.x < 10) sb[threadIdx.x] = cb[threadIdx.x];
    __syncthreads();
    int g = blockIdx.x * blockDim.x + threadIdx.x;
    if (g >= G) return;
    float h[64];
    const float4* hp = (const float4*)(g_acc2 + (size_t)g * 16);
#pragma unroll
    for (int j = 0; j < 16; j++) {
        float4 w = hp[j];
        w.x = fmaxf(w.x, 0.f); w.y = fmaxf(w.y, 0.f);
        w.z = fmaxf(w.z, 0.f); w.w = fmaxf(w.w, 0.f);
        ((float4*)h)[j] = w;
    }
    float o[10];
#pragma unroll
    for (int c = 0; c < 10; c++) o[c] = sb[c];
#pragma unroll 8
    for (int k = 0; k < 64; k++) {
        float hk = h[k];
#pragma unroll
        for (int c = 0; c < 10; c++) o[c] = fmaf(hk, Ws[k * 10 + c], o[c]);
    }
#pragma unroll
    for (int c = 0; c < 10; c++) out[(size_t)g * 10 + c] = o[c];
}

extern "C" void kernel_launch(void* const* d_in, const int* in_sizes, int n_in,
                              void* d_out, int out_size)
{
    const int*   x      = (const int*)d_in[0];
    const int*   ei     = (const int*)d_in[1];
    const int*   et     = (const int*)d_in[2];
    const int*   ptr    = (const int*)d_in[3];
    const float* se     = (const float*)d_in[4];
    const float* ce     = (const float*)d_in[5];
    const float* pw     = (const float*)d_in[6];
    const float* pb     = (const float*)d_in[7];
    const float* w1rel  = (const float*)d_in[8];
    const float* w1root = (const float*)d_in[9];
    const float* b1     = (const float*)d_in[10];
    const float* w2rel  = (const float*)d_in[11];
    const float* w2root = (const float*)d_in[12];
    const float* b2     = (const float*)d_in[13];
    const float* cw     = (const float*)d_in[14];
    const float* cb     = (const float*)d_in[15];
    float* out = (float*)d_out;

    int n = in_sizes[0] / 2;       // nodes
    int E = in_sizes[1] / 2;       // edges
    int G = in_sizes[3] - 1;       // graphs

    k_init<<<4096, 256>>>(n, 3 * n);
    k_rank<<<(G + 255) / 256, 256>>>(ptr, G);
    k_part<<<(E + 255) / 256, 256>>>(ei, et, E, n);
    k_inv<<<4096, 256>>>(3 * n);
    k_node1<<<(n + 255) / 256, 256>>>(x, se, ce, pw, pb, w1root, b1, n);
    k_edge1<<<dim3(1536, 3), 256>>>(w1rel, n);
    k_node2<<<(G + 255) / 256, 256>>>(ptr, w2root, b2, G);
    k_edge2<<<512, 256>>>(w2rel, n);
    k_cls<<<(G + 255) / 256, 256>>>(cw, cb, out, G);
}

// round 3
// speedup vs baseline: 5.1507x; 5.1507x over previous
#include <cuda_runtime.h>

typedef unsigned long long u64;

#define NMAX 500000
#define EMAX 1000000
#define GMAX 5000

// ---- persistent scratch (no runtime allocation allowed) ----
__device__ int    g_rank[NMAX];                  // node -> graph rank (or -1)
__device__ int    g_s1flag[NMAX];                // node needs h1?
__device__ int    g_idx1[NMAX];                  // node -> compact S1 index
__device__ int    g_s1nodes[NMAX];               // compact S1 index -> node
__device__ int    g_cnt1[3 * NMAX];              // [s1idx*3 + r] in-edge count (layer1)
__device__ int    g_cnt2[3 * GMAX];              // [g*3 + r] in-edge count at targets
__device__ float  g_agg1[(size_t)NMAX * 96];     // [s1idx][r][32] raw h0 sums
__device__ float  g_agg2[GMAX * 192];            // [g][r][64] raw h1 sums
__device__ float  g_acc2[GMAX * 64];             // [g][64] b2 + h1[tgt] @ w2_root
__device__ float4 g_h1[(size_t)NMAX * 16];       // [s1idx][64] relu'd layer-1 output
__device__ int4   g_L1[EMAX];                    // layer-1 edges (src, s1idx_dst, rel, -)
__device__ int4   g_L2[EMAX];                    // layer-2 edges (src, grank, rel, -)
__device__ int    g_ctr[8];                      // 0=L2 count, 1=S1 count, 2=L1 count

// ---- packed f32x2 helpers ----
__device__ __forceinline__ u64 pack2(float x, float y) {
    u64 d;
    asm("mov.b64 %0, {%1, %2};" : "=l"(d) : "r"(__float_as_uint(x)), "r"(__float_as_uint(y)));
    return d;
}
__device__ __forceinline__ void unpack2(u64 v, float& x, float& y) {
    unsigned a, b;
    asm("mov.b64 {%0, %1}, %2;" : "=r"(a), "=r"(b) : "l"(v));
    x = __uint_as_float(a); y = __uint_as_float(b);
}
__device__ __forceinline__ u64 fma2(u64 a, u64 b, u64 c) {
    u64 d;
    asm("fma.rn.f32x2 %0, %1, %2, %3;" : "=l"(d) : "l"(a), "l"(b), "l"(c));
    return d;
}
__device__ __forceinline__ void red4(float* p, float a, float b, float c, float d) {
    asm volatile("red.global.add.v4.f32 [%0], {%1, %2, %3, %4};"
                 :: "l"(p), "f"(a), "f"(b), "f"(c), "f"(d) : "memory");
}

// ---- on-the-fly h0: emb concat -> pre layer -> relu (weights in smem) ----
__device__ __forceinline__ void compute_h0(
    int node, const int* __restrict__ x,
    const float* s_se, const float* s_ce,
    const float* s_pw, const float* s_pb, float* h)
{
    int x0 = __ldg(&x[2 * node]);
    int x1 = __ldg(&x[2 * node + 1]);
    float v[16];
    const float4* sp = (const float4*)(s_se + x0 * 8);
    const float4* cp = (const float4*)(s_ce + x1 * 8);
    ((float4*)v)[0] = sp[0]; ((float4*)v)[1] = sp[1];
    ((float4*)v)[2] = cp[0]; ((float4*)v)[3] = cp[1];

    u64 m[16];
#pragma unroll
    for (int j = 0; j < 16; j++) m[j] = pack2(s_pb[2 * j], s_pb[2 * j + 1]);
#pragma unroll
    for (int k = 0; k < 16; k++) {
        u64 hk = pack2(v[k], v[k]);
        const ulonglong2* row = (const ulonglong2*)(s_pw + k * 32);
#pragma unroll
        for (int j = 0; j < 8; j++) {
            ulonglong2 w = row[j];
            m[2 * j]     = fma2(hk, w.x, m[2 * j]);
            m[2 * j + 1] = fma2(hk, w.y, m[2 * j + 1]);
        }
    }
#pragma unroll
    for (int j = 0; j < 16; j++) {
        float a, b; unpack2(m[j], a, b);
        h[2 * j] = fmaxf(a, 0.f); h[2 * j + 1] = fmaxf(b, 0.f);
    }
}

// ---- init: clear flags/counts/counters ----
__global__ void k_init(int n, int G) {
    int i = blockIdx.x * blockDim.x + threadIdx.x;
    int stride = gridDim.x * blockDim.x;
    for (int j = i; j < 3 * n; j += stride) g_cnt1[j] = 0;
    for (int j = i; j < n; j += stride) { g_rank[j] = -1; g_s1flag[j] = 0; }
    for (int j = i; j < 3 * G * 64; j += stride) g_agg2[j] = 0.f;
    for (int j = i; j < 3 * G; j += stride) g_cnt2[j] = 0;
    if (i < 8) g_ctr[i] = 0;
}

// ---- mark targets (last node of each graph); targets also need h1 ----
__global__ void k_rank(const int* __restrict__ ptr, int G) {
    int g = blockIdx.x * blockDim.x + threadIdx.x;
    if (g < G) {
        int t = ptr[g + 1] - 1;
        g_rank[t] = g;
        g_s1flag[t] = 1;
    }
}

// ---- pass A over all edges: collect layer-2 edges (dst is a target) ----
__global__ void k_passA(const int* __restrict__ ei, const int* __restrict__ et, int E) {
    int e = blockIdx.x * blockDim.x + threadIdx.x;
    if (e >= E) return;
    int s = ei[e];
    int d = ei[E + e];
    int rk = g_rank[d];
    if (rk >= 0) {
        int r = et[e];
        int p = atomicAdd(&g_ctr[0], 1);
        g_L2[p] = make_int4(s, rk, r, 0);
        atomicAdd(&g_cnt2[rk * 3 + r], 1);
        g_s1flag[s] = 1;
    }
}

// ---- compact S1 set ----
__global__ void k_compact(int n) {
    int i = blockIdx.x * blockDim.x + threadIdx.x;
    if (i < n && g_s1flag[i]) {
        int p = atomicAdd(&g_ctr[1], 1);
        g_s1nodes[p] = i;
        g_idx1[i] = p;
    }
}

// ---- clear agg1 for the live S1 region (size known only on device) ----
__global__ void k_clear1() {
    int m = g_ctr[1] * 96;
    int stride = gridDim.x * blockDim.x;
    for (int j = blockIdx.x * blockDim.x + threadIdx.x; j < m; j += stride)
        g_agg1[j] = 0.f;
}

// ---- pass B over all edges: collect layer-1 edges (dst in S1) + counts ----
__global__ void k_passB(const int* __restrict__ ei, const int* __restrict__ et, int E) {
    int e = blockIdx.x * blockDim.x + threadIdx.x;
    if (e >= E) return;
    int d = ei[E + e];
    if (g_s1flag[d]) {
        int s = ei[e];
        int r = et[e];
        int p = g_idx1[d];
        atomicAdd(&g_cnt1[p * 3 + r], 1);
        int q = atomicAdd(&g_ctr[2], 1);
        g_L1[q] = make_int4(s, p, r, 0);
    }
}

// ---- layer-1 aggregation: scatter raw h0[src] into agg1[s1idx][rel] ----
__global__ __launch_bounds__(256) void k_h1agg(
    const int* __restrict__ x, const float* __restrict__ se, const float* __restrict__ ce,
    const float* __restrict__ pw, const float* __restrict__ pb)
{
    __shared__ __align__(16) float s_se[128], s_ce[128], s_pw[512], s_pb[32];
    int t = threadIdx.x;
    if (t < 128) { s_se[t] = se[t]; s_ce[t] = ce[t]; }
    for (int j = t; j < 512; j += 256) s_pw[j] = pw[j];
    if (t < 32) s_pb[t] = pb[t];
    __syncthreads();

    int cnt = g_ctr[2];
    int stride = gridDim.x * 256;
    for (int idx = blockIdx.x * 256 + t; idx < cnt; idx += stride) {
        int4 e = g_L1[idx];
        float h[32];
        compute_h0(e.x, x, s_se, s_ce, s_pw, s_pb, h);
        float* dp = g_agg1 + (size_t)e.y * 96 + e.z * 32;
#pragma unroll
        for (int j = 0; j < 8; j++)
            red4(dp + 4 * j, h[4 * j], h[4 * j + 1], h[4 * j + 2], h[4 * j + 3]);
    }
}

// ---- layer-1 transform at S1 nodes: h1 = relu(b1 + h0@root + sum_r mean_r@W_r) ----
__global__ __launch_bounds__(256) void k_h1(
    const int* __restrict__ x, const float* __restrict__ se, const float* __restrict__ ce,
    const float* __restrict__ pw, const float* __restrict__ pb,
    const float* __restrict__ w1rel, const float* __restrict__ w1root,
    const float* __restrict__ b1)
{
    __shared__ __align__(16) float s_se[128], s_ce[128], s_pw[512], s_pb[32];
    __shared__ __align__(16) float s_root[2048];   // [32,64]
    __shared__ __align__(16) float s_rel[6144];    // [3,32,64]
    __shared__ float s_b1[64];
    int t = threadIdx.x;
    if (t < 128) { s_se[t] = se[t]; s_ce[t] = ce[t]; }
    for (int j = t; j < 512;  j += 256) s_pw[j] = pw[j];
    for (int j = t; j < 2048; j += 256) s_root[j] = w1root[j];
    for (int j = t; j < 6144; j += 256) s_rel[j] = w1rel[j];
    if (t < 32) s_pb[t] = pb[t];
    if (t < 64) s_b1[t] = b1[t];
    __syncthreads();

    int cnt = g_ctr[1];
    int stride = gridDim.x * 256;
    for (int p = blockIdx.x * 256 + t; p < cnt; p += stride) {
        int node = g_s1nodes[p];
        float h0[32];
        compute_h0(node, x, s_se, s_ce, s_pw, s_pb, h0);

        u64 m[32];
#pragma unroll
        for (int j = 0; j < 32; j++) m[j] = pack2(s_b1[2 * j], s_b1[2 * j + 1]);
#pragma unroll 4
        for (int k = 0; k < 32; k++) {
            u64 hk = pack2(h0[k], h0[k]);
            const ulonglong2* row = (const ulonglong2*)(s_root + k * 64);
#pragma unroll
            for (int j = 0; j < 16; j++) {
                ulonglong2 w = row[j];
                m[2 * j]     = fma2(hk, w.x, m[2 * j]);
                m[2 * j + 1] = fma2(hk, w.y, m[2 * j + 1]);
            }
        }
        for (int r = 0; r < 3; r++) {
            int c = g_cnt1[p * 3 + r];
            if (c > 0) {
                float inv = 1.0f / (float)c;
                float a[32];
                const float4* ap = (const float4*)(g_agg1 + (size_t)p * 96 + r * 32);
#pragma unroll
                for (int j = 0; j < 8; j++) ((float4*)a)[j] = ap[j];
                const float* wr = s_rel + r * 2048;
#pragma unroll 4
                for (int k = 0; k < 32; k++) {
                    float av = a[k] * inv;
                    u64 hk = pack2(av, av);
                    const ulonglong2* row = (const ulonglong2*)(wr + k * 64);
#pragma unroll
                    for (int j = 0; j < 16; j++) {
                        ulonglong2 w = row[j];
                        m[2 * j]     = fma2(hk, w.x, m[2 * j]);
                        m[2 * j + 1] = fma2(hk, w.y, m[2 * j + 1]);
                    }
                }
            }
        }
        float o[64];
#pragma unroll
        for (int j = 0; j < 32; j++) unpack2(m[j], o[2 * j], o[2 * j + 1]);
        float4* hp = (float4*)(g_h1 + (size_t)p * 16);
#pragma unroll
        for (int j = 0; j < 16; j++) {
            float4 w = ((float4*)o)[j];
            w.x = fmaxf(w.x, 0.f); w.y = fmaxf(w.y, 0.f);
            w.z = fmaxf(w.z, 0.f); w.w = fmaxf(w.w, 0.f);
            hp[j] = w;
        }
    }
}

// ---- layer-2 root term: acc2[g] = b2 + h1[tgt] @ w2_root ----
__global__ __launch_bounds__(256) void k_root2(
    const int* __restrict__ ptr, const float* __restrict__ w2root,
    const float* __restrict__ b2, int G)
{
    __shared__ __align__(16) float s_w[4096];
    __shared__ float s_b[64];
    int t = threadIdx.x;
    for (int j = t; j < 4096; j += 256) s_w[j] = w2root[j];
    if (t < 64) s_b[t] = b2[t];
    __syncthreads();
    int g = blockIdx.x * 256 + t;
    if (g >= G) return;
    int tgt = ptr[g + 1] - 1;
    int p = g_idx1[tgt];

    float h[64];
    const float4* hp = (const float4*)(g_h1 + (size_t)p * 16);
#pragma unroll
    for (int j = 0; j < 16; j++) ((float4*)h)[j] = hp[j];

    u64 m[32];
#pragma unroll
    for (int j = 0; j < 32; j++) m[j] = pack2(s_b[2 * j], s_b[2 * j + 1]);
#pragma unroll 4
    for (int k = 0; k < 64; k++) {
        u64 hk = pack2(h[k], h[k]);
        const ulonglong2* row = (const ulonglong2*)(s_w + k * 64);
#pragma unroll
        for (int j = 0; j < 16; j++) {
            ulonglong2 w = row[j];
            m[2 * j]     = fma2(hk, w.x, m[2 * j]);
            m[2 * j + 1] = fma2(hk, w.y, m[2 * j + 1]);
        }
    }
    float o[64];
#pragma unroll
    for (int j = 0; j < 32; j++) unpack2(m[j], o[2 * j], o[2 * j + 1]);
    float4* ap = (float4*)(g_acc2 + (size_t)g * 64);
#pragma unroll
    for (int j = 0; j < 16; j++) ap[j] = ((float4*)o)[j];
}

// ---- layer-2 aggregation: scatter h1[src] into agg2[g][rel] ----
__global__ __launch_bounds__(256) void k_h2agg() {
    int cnt = g_ctr[0];
    int stride = gridDim.x * 256;
    for (int idx = blockIdx.x * 256 + threadIdx.x; idx < cnt; idx += stride) {
        int4 e = g_L2[idx];
        int p = g_idx1[e.x];
        const float4* hp = (const float4*)(g_h1 + (size_t)p * 16);
        float* dp = g_agg2 + (size_t)e.y * 192 + e.z * 64;
#pragma unroll
        for (int j = 0; j < 16; j++) {
            float4 w = hp[j];
            red4(dp + 4 * j, w.x, w.y, w.z, w.w);
        }
    }
}

// ---- final: out[g] = relu(acc2 + sum_r mean2_r @ W2_r) @ cls_w + cls_b ----
__global__ __launch_bounds__(256) void k_out(
    const float* __restrict__ w2rel, const float* __restrict__ cls,
    const float* __restrict__ cb, float* __restrict__ out, int G)
{
    __shared__ __align__(16) float s_w[12288];  // [3,64,64] = 48KB
    int t = threadIdx.x;
    for (int j = t; j < 12288; j += 256) s_w[j] = w2rel[j];
    __syncthreads();
    int g = blockIdx.x * 256 + t;
    if (g >= G) return;

    u64 m[32];
    {
        float racc[64];
        const float4* rp = (const float4*)(g_acc2 + (size_t)g * 64);
#pragma unroll
        for (int j = 0; j < 16; j++) ((float4*)racc)[j] = rp[j];
#pragma unroll
        for (int j = 0; j < 32; j++) m[j] = pack2(racc[2 * j], racc[2 * j + 1]);
    }
    for (int r = 0; r < 3; r++) {
        int c = g_cnt2[g * 3 + r];
        if (c > 0) {
            float inv = 1.0f / (float)c;
            float a[64];
            const float4* ap = (const float4*)(g_agg2 + (size_t)g * 192 + r * 64);
#pragma unroll
            for (int j = 0; j < 16; j++) ((float4*)a)[j] = ap[j];
            const float* wr = s_w + r * 4096;
#pragma unroll 4
            for (int k = 0; k < 64; k++) {
                float av = a[k] * inv;
                u64 hk = pack2(av, av);
                const ulonglong2* row = (const ulonglong2*)(wr + k * 64);
#pragma unroll
                for (int j = 0; j < 16; j++) {
                    ulonglong2 w = row[j];
                    m[2 * j]     = fma2(hk, w.x, m[2 * j]);
                    m[2 * j + 1] = fma2(hk, w.y, m[2 * j + 1]);
                }
            }
        }
    }
    float o[64];
#pragma unroll
    for (int j = 0; j < 32; j++) {
        float a, b; unpack2(m[j], a, b);
        o[2 * j] = fmaxf(a, 0.f); o[2 * j + 1] = fmaxf(b, 0.f);
    }
    float res[10];
#pragma unroll
    for (int c = 0; c < 10; c++) res[c] = __ldg(&cb[c]);
#pragma unroll 8
    for (int k = 0; k < 64; k++) {
        float hk = o[k];
#pragma unroll
        for (int c = 0; c < 10; c++) res[c] = fmaf(hk, __ldg(&cls[k * 10 + c]), res[c]);
    }
#pragma unroll
    for (int c = 0; c < 10; c++) out[(size_t)g * 10 + c] = res[c];
}

extern "C" void kernel_launch(void* const* d_in, const int* in_sizes, int n_in,
                              void* d_out, int out_size)
{
    const int*   x      = (const int*)d_in[0];
    const int*   ei     = (const int*)d_in[1];
    const int*   et     = (const int*)d_in[2];
    const int*   ptr    = (const int*)d_in[3];
    const float* se     = (const float*)d_in[4];
    const float* ce     = (const float*)d_in[5];
    const float* pw     = (const float*)d_in[6];
    const float* pb     = (const float*)d_in[7];
    const float* w1rel  = (const float*)d_in[8];
    const float* w1root = (const float*)d_in[9];
    const float* b1     = (const float*)d_in[10];
    const float* w2rel  = (const float*)d_in[11];
    const float* w2root = (const float*)d_in[12];
    const float* b2     = (const float*)d_in[13];
    const float* cw     = (const float*)d_in[14];
    const float* cb     = (const float*)d_in[15];
    float* out = (float*)d_out;

    int n = in_sizes[0] / 2;       // nodes
    int E = in_sizes[1] / 2;       // edges
    int G = in_sizes[3] - 1;       // graphs

    k_init<<<2048, 256>>>(n, G);
    k_rank<<<(G + 255) / 256, 256>>>(ptr, G);
    k_passA<<<(E + 255) / 256, 256>>>(ei, et, E);
    k_compact<<<(n + 255) / 256, 256>>>(n);
    k_clear1<<<512, 256>>>();
    k_passB<<<(E + 255) / 256, 256>>>(ei, et, E);
    k_h1agg<<<296, 256>>>(x, se, ce, pw, pb);
    k_h1<<<296, 256>>>(x, se, ce, pw, pb, w1rel, w1root, b1);
    k_root2<<<(G + 255) / 256, 256>>>(ptr, w2root, b2, G);
    k_h2agg<<<296, 256>>>();
    k_out<<<(G + 255) / 256, 256>>>(w2rel, cw, cb, out, G);
}